// round 5
// baseline (speedup 1.0000x reference)
#include <cuda_runtime.h>
#include <cuda.h>
#include <cuda_bf16.h>
#include <math.h>
#include <stdint.h>

// LongcatFlashTopkRouter: T=16384, D=4096, E=256
#define TOP_K 8
#define ROUTED_SCALE 1.5f

#if defined(__CUDA_ARCH__) && \
    (defined(__CUDA_ARCH_FEAT_SM103_ALL) || defined(__CUDA_ARCH_FEAT_SM100_ALL) || \
     defined(__CUDA_ARCH_FEAT_SM101_ALL))
#define HAS_TC 1
#else
#define HAS_TC 0
#endif

#define BM 128
#define BKF 32
#define NSTAGE 4
#define STAGE_BYTES 32768          // B_hi 16KB + B_lo 16KB (bf16, 256 rows x 32 cols)
#define B_LO_OFF 16384
#define DYN_SMEM (NSTAGE * STAGE_BYTES + 1024)
#define CLUSTER_N 4

// idesc kind::f16 bf16: F32(1)<<4 | BF16(1)<<7 | BF16(1)<<10 | (N=128/8)<<17 | (M=128/16)<<24
#define IDESC 0x8200490u
#define TMEM_NCOLS 512
#define TMEM_A_BASE 256            // A stages: cols 256 + s*32 (hi 16 cols, lo 16 cols)

// W split into bf16 hi/lo, done once per launch by a prep kernel.
// 256*4096 bf16 each = 2MB each. Static device arrays (no runtime alloc).
__device__ __align__(1024) static uint32_t g_w_hi[524288];
__device__ __align__(1024) static uint32_t g_w_lo[524288];

// d = { high = bf16(a), low = bf16(b) }
__device__ __forceinline__ uint32_t pack_bf16x2(float a, float b) {
    uint32_t d;
    asm("cvt.rn.bf16x2.f32 %0, %1, %2;" : "=r"(d) : "f"(a), "f"(b));
    return d;
}

__device__ __forceinline__ uint32_t smem_u32(const void* p) {
    uint32_t a;
    asm("{ .reg .u64 t; cvta.to.shared.u64 t, %1; cvt.u32.u64 %0, t; }" : "=r"(a) : "l"(p));
    return a;
}

// ------------------------- prep: split W fp32 -> bf16 hi/lo ------------------
__global__ __launch_bounds__(256)
void split_w_kernel(const float4* __restrict__ W4, int n4) {
    int i = blockIdx.x * 256 + threadIdx.x;
    if (i >= n4) return;
    float4 f = W4[i];
    uint32_t h0 = pack_bf16x2(f.y, f.x);   // low half = x, high = y
    uint32_t h1 = pack_bf16x2(f.w, f.z);
    float a0 = __uint_as_float(h0 << 16);
    float a1 = __uint_as_float(h0 & 0xFFFF0000u);
    float a2 = __uint_as_float(h1 << 16);
    float a3 = __uint_as_float(h1 & 0xFFFF0000u);
    uint32_t l0 = pack_bf16x2(f.y - a1, f.x - a0);
    uint32_t l1 = pack_bf16x2(f.w - a3, f.z - a2);
    g_w_hi[i * 2]     = h0;
    g_w_hi[i * 2 + 1] = h1;
    g_w_lo[i * 2]     = l0;
    g_w_lo[i * 2 + 1] = l1;
}

#if HAS_TC
// SW64 K-major descriptor: layout=4, version=1, SBO=32 (512B / 8 rows), LBO=1
__device__ __forceinline__ uint64_t mk_desc64(uint32_t addr) {
    const uint64_t base =
        (uint64_t(4) << 61) | (uint64_t(1) << 46) | (uint64_t(32) << 32) | (uint64_t(1) << 16);
    return base | ((uint64_t)(addr >> 4) & 0x3FFF);
}

// TS-form bf16 MMA: A in TMEM, B in SMEM
__device__ __forceinline__ void mma_ts(uint32_t d_tmem, uint32_t a_tmem, uint64_t b_desc,
                                       uint32_t en) {
    uint32_t z = 0;
    asm volatile(
        "{\n\t.reg .pred p;\n\t"
        "setp.ne.u32 p, %5, 0;\n\t"
        "tcgen05.mma.cta_group::1.kind::f16 [%0], [%1], %2, %3, {%4, %4, %4, %4}, p;\n\t}"
        :: "r"(d_tmem), "r"(a_tmem), "l"(b_desc), "r"(IDESC), "r"(z), "r"(en)
        : "memory");
}

__device__ __forceinline__ void mbar_init(uint32_t mbar, uint32_t cnt) {
    asm volatile("mbarrier.init.shared.b64 [%0], %1;" :: "r"(mbar), "r"(cnt) : "memory");
}

__device__ __forceinline__ void mbar_wait(uint32_t mbar, uint32_t parity) {
    asm volatile(
        "{\n\t.reg .pred P;\n\t"
        "WL_%=:\n\t"
        "mbarrier.try_wait.parity.acquire.cta.shared::cta.b64 P, [%0], %1, 0x989680;\n\t"
        "@P bra.uni WD_%=;\n\t"
        "bra.uni WL_%=;\n\t"
        "WD_%=:\n\t}"
        :: "r"(mbar), "r"(parity) : "memory");
}

__device__ __forceinline__ void mbar_expect_tx(uint32_t mbar, uint32_t bytes) {
    asm volatile("mbarrier.arrive.expect_tx.shared.b64 _, [%0], %1;"
                 :: "r"(mbar), "r"(bytes) : "memory");
}

__device__ __forceinline__ void tma_2d_mc(uint32_t dst, const void* map,
                                          int x, int y, uint32_t mbar, uint16_t mask) {
    asm volatile(
        "cp.async.bulk.tensor.2d.shared::cluster.global.tile.mbarrier::complete_tx::bytes"
        ".multicast::cluster [%0], [%1, {%2, %3}], [%4], %5;"
        :: "r"(dst), "l"(map), "r"(x), "r"(y), "r"(mbar), "h"(mask) : "memory");
}

__device__ __forceinline__ uint32_t cta_rank() {
    uint32_t r;
    asm("mov.u32 %0, %%cluster_ctarank;" : "=r"(r));
    return r;
}

#define TC_ALLOC(dst_smem, n) \
    asm volatile("tcgen05.alloc.cta_group::1.sync.aligned.shared::cta.b32 [%0], %1;" \
                 :: "r"(dst_smem), "r"((uint32_t)(n)) : "memory")
#define TC_RELINQ() \
    asm volatile("tcgen05.relinquish_alloc_permit.cta_group::1.sync.aligned;")
#define TC_DEALLOC(tm, n) \
    asm volatile("tcgen05.dealloc.cta_group::1.sync.aligned.b32 %0, %1;" :: "r"(tm), "r"((uint32_t)(n)))
#define TC_COMMIT_MC(mbar, mask) \
    asm volatile("tcgen05.commit.cta_group::1.mbarrier::arrive::one.shared::cluster" \
                 ".multicast::cluster.b64 [%0], %1;" \
                 :: "r"(mbar), "h"((uint16_t)(mask)) : "memory")
#define TC_FENCE_AFTER()  asm volatile("tcgen05.fence::after_thread_sync;" ::: "memory")
#define TC_FENCE_BEFORE() asm volatile("tcgen05.fence::before_thread_sync;" ::: "memory")
#define TC_WAIT_ST()  asm volatile("tcgen05.wait::st.sync.aligned;" ::: "memory")
#define TC_WAIT_LD()  asm volatile("tcgen05.wait::ld.sync.aligned;" ::: "memory")
#define CLUSTER_SYNC() do { \
    asm volatile("barrier.cluster.arrive.aligned;" ::: "memory"); \
    asm volatile("barrier.cluster.wait.aligned;" ::: "memory"); } while (0)

#define TC_ST_X8(addr, r) \
    asm volatile("tcgen05.st.sync.aligned.32x32b.x8.b32 [%0], {%1,%2,%3,%4,%5,%6,%7,%8};" \
        :: "r"(addr), "r"((r)[0]), "r"((r)[1]), "r"((r)[2]), "r"((r)[3]), \
           "r"((r)[4]), "r"((r)[5]), "r"((r)[6]), "r"((r)[7]) : "memory")

#define TC_LD_X32(r, addr) \
    asm volatile( \
        "tcgen05.ld.sync.aligned.32x32b.x32.b32 " \
        "{%0, %1, %2, %3, %4, %5, %6, %7, " \
        " %8, %9, %10, %11, %12, %13, %14, %15, " \
        " %16, %17, %18, %19, %20, %21, %22, %23, " \
        " %24, %25, %26, %27, %28, %29, %30, %31}, [%32];" \
        : "=r"((r)[0]),  "=r"((r)[1]),  "=r"((r)[2]),  "=r"((r)[3]), \
          "=r"((r)[4]),  "=r"((r)[5]),  "=r"((r)[6]),  "=r"((r)[7]), \
          "=r"((r)[8]),  "=r"((r)[9]),  "=r"((r)[10]), "=r"((r)[11]), \
          "=r"((r)[12]), "=r"((r)[13]), "=r"((r)[14]), "=r"((r)[15]), \
          "=r"((r)[16]), "=r"((r)[17]), "=r"((r)[18]), "=r"((r)[19]), \
          "=r"((r)[20]), "=r"((r)[21]), "=r"((r)[22]), "=r"((r)[23]), \
          "=r"((r)[24]), "=r"((r)[25]), "=r"((r)[26]), "=r"((r)[27]), \
          "=r"((r)[28]), "=r"((r)[29]), "=r"((r)[30]), "=r"((r)[31]) \
        : "r"(addr))
#endif  // HAS_TC

extern __shared__ char g_dyn_smem[];

__global__ __launch_bounds__(256, 1) __cluster_dims__(CLUSTER_N, 1, 1)
void gemm_kernel(const float* __restrict__ A,   // [T, D]
                 float* __restrict__ C,         // [T, E]
                 int D, int E,
                 const float* __restrict__ W,   // fp32 W (fallback only)
                 const __grid_constant__ CUtensorMap tm_hi,
                 const __grid_constant__ CUtensorMap tm_lo) {
#if HAS_TC
    // ============ tcgen05 bf16x3, A->TMEM (TS), B via TMA multicast ==========
    __shared__ uint32_t s_tmem;
    __shared__ __align__(16) unsigned long long s_mbar[2 * NSTAGE];  // full[4], empty[4]

    const int tid  = threadIdx.x;
    const int wid  = tid >> 5;
    const int lane = tid & 31;
    const uint32_t rank = cta_rank();

    uint32_t raw_u32  = smem_u32(g_dyn_smem);
    uint32_t btile_u32 = (raw_u32 + 1023u) & ~1023u;

    const uint32_t mb   = smem_u32(&s_mbar[0]);
    const uint32_t FULL = mb;            // full[s] at mb + s*8
    const uint32_t EMPT = mb + 32;       // empty[s] at mb + 32 + s*8

    if (wid == 0) TC_ALLOC(smem_u32(&s_tmem), TMEM_NCOLS);
    if (tid == 0) {
        #pragma unroll
        for (int s = 0; s < NSTAGE; s++) {
            mbar_init(FULL + s * 8, 1);
            mbar_init(EMPT + s * 8, CLUSTER_N);   // 4 commits (one multicast per CTA)
        }
    }
    __syncthreads();
    CLUSTER_SYNC();   // all mbars visible cluster-wide before any multicast
    const uint32_t tmem = s_tmem;

    const int blockRow = blockIdx.x * BM;
    const int niter = D / BKF;            // 128
    const int subp  = wid & 3;            // TMEM subpartition
    const int kh    = wid >> 2;           // K-half (0: cols 0-15, 1: cols 16-31)

    // A: thread owns row (subp*32 + lane), 16 fp32 of each K-chunk (half kh)
    const float* aBase = A + (size_t)(blockRow + subp * 32 + lane) * D + kh * 16;

    // prologue: TMA for iters 0..2 (all round 0, no empty gate)
    if (tid == 0) {
        #pragma unroll
        for (int j = 0; j < NSTAGE - 1; j++) {
            const uint32_t sb = btile_u32 + (uint32_t)j * STAGE_BYTES;
            mbar_expect_tx(FULL + j * 8, STAGE_BYTES);
            tma_2d_mc(sb + rank * 4096,            &tm_hi, j * 32, (int)rank * 64,
                      FULL + j * 8, (uint16_t)0xF);
            tma_2d_mc(sb + B_LO_OFF + rank * 4096, &tm_lo, j * 32, (int)rank * 64,
                      FULL + j * 8, (uint16_t)0xF);
        }
    }

    float4 buf[4];
    #pragma unroll
    for (int q = 0; q < 4; q++) buf[q] = *(const float4*)(aBase + q * 4);

    uint32_t en = 0;

    for (int i = 0; i < niter; i++) {
        const int s = i & 3;
        const int r = i >> 2;

        // gate: A-TMEM stage s reusable once round r-1's MMA committed (all CTAs)
        if (r > 0) mbar_wait(EMPT + s * 8, (r - 1) & 1);

        // TMA-ahead for iter j = i+3
        if (tid == 0) {
            const int j = i + NSTAGE - 1;
            if (j < niter) {
                const int sj = j & 3, rj = j >> 2;
                if (rj > 0) mbar_wait(EMPT + sj * 8, (rj - 1) & 1);
                const uint32_t sb = btile_u32 + (uint32_t)sj * STAGE_BYTES;
                mbar_expect_tx(FULL + sj * 8, STAGE_BYTES);
                tma_2d_mc(sb + rank * 4096,            &tm_hi, j * 32, (int)rank * 64,
                          FULL + sj * 8, (uint16_t)0xF);
                tma_2d_mc(sb + B_LO_OFF + rank * 4096, &tm_lo, j * 32, (int)rank * 64,
                          FULL + sj * 8, (uint16_t)0xF);
            }
        }

        // ---- A: convert fp32 -> hi/lo bf16x2, store to TMEM stage s ----
        {
            uint32_t hi[8], lo[8];
            #pragma unroll
            for (int q = 0; q < 4; q++) {
                float4 f = buf[q];
                uint32_t h0 = pack_bf16x2(f.y, f.x);
                uint32_t h1 = pack_bf16x2(f.w, f.z);
                float a0 = __uint_as_float(h0 << 16);
                float a1 = __uint_as_float(h0 & 0xFFFF0000u);
                float a2 = __uint_as_float(h1 << 16);
                float a3 = __uint_as_float(h1 & 0xFFFF0000u);
                hi[q * 2]     = h0;
                hi[q * 2 + 1] = h1;
                lo[q * 2]     = pack_bf16x2(f.y - a1, f.x - a0);
                lo[q * 2 + 1] = pack_bf16x2(f.w - a3, f.z - a2);
            }
            const uint32_t ac = tmem + ((uint32_t)subp << 21) +
                                TMEM_A_BASE + (uint32_t)s * 32 + (uint32_t)kh * 8;
            TC_ST_X8(ac, hi);
            TC_ST_X8(ac + 16, lo);
            TC_WAIT_ST();
        }

        // prefetch next A chunk
        if (i + 1 < niter) {
            const float* ap = aBase + (i + 1) * BKF;
            #pragma unroll
            for (int q = 0; q < 4; q++) buf[q] = *(const float4*)(ap + q * 4);
        }

        TC_FENCE_BEFORE();
        __syncthreads();

        if (tid == 0) {
            mbar_wait(FULL + s * 8, r & 1);   // B tile landed
            TC_FENCE_AFTER();
            const uint32_t sb = btile_u32 + (uint32_t)s * STAGE_BYTES;
            const uint64_t dBh = mk_desc64(sb);
            const uint64_t dBl = mk_desc64(sb + B_LO_OFF);
            const uint32_t ab = tmem + TMEM_A_BASE + (uint32_t)s * 32;
            #pragma unroll
            for (int ks = 0; ks < 2; ks++) {
                const uint64_t o = 2 * ks;       // K-step: 16 bf16 = 32B = 2 units
                const uint32_t aH = ab + ks * 8;
                const uint32_t aL = ab + 16 + ks * 8;
                mma_ts(tmem,       aH, dBh + o,       en);
                mma_ts(tmem + 128, aH, dBh + 512 + o, en);   // rows 128-255: +8192B
                en = 1;
                mma_ts(tmem,       aH, dBl + o,       1);
                mma_ts(tmem + 128, aH, dBl + 512 + o, 1);
                mma_ts(tmem,       aL, dBh + o,       1);
                mma_ts(tmem + 128, aL, dBh + 512 + o, 1);
            }
            TC_COMMIT_MC(EMPT + s * 8, 0xF);
        }
    }

    // drain: final round (31) commits on all stages
    #pragma unroll
    for (int s = 0; s < NSTAGE; s++) mbar_wait(EMPT + s * 8, 1);
    TC_FENCE_AFTER();

    // epilogue: warps 0-3 read D (128x256 fp32) from TMEM
    if (wid < 4) {
        const int m = blockRow + wid * 32 + lane;
        #pragma unroll
        for (int cb = 0; cb < 256; cb += 32) {
            uint32_t rg[32];
            TC_LD_X32(rg, tmem + cb);
            TC_WAIT_LD();
            float* cr = C + (size_t)m * E + cb;
            #pragma unroll
            for (int q = 0; q < 8; q++) {
                *(float4*)(cr + q * 4) = make_float4(__uint_as_float(rg[q * 4 + 0]),
                                                     __uint_as_float(rg[q * 4 + 1]),
                                                     __uint_as_float(rg[q * 4 + 2]),
                                                     __uint_as_float(rg[q * 4 + 3]));
            }
        }
        TC_FENCE_BEFORE();
    }
    __syncthreads();
    if (wid == 0) {
        TC_RELINQ();
        TC_DEALLOC(tmem, TMEM_NCOLS);
    }
    CLUSTER_SYNC();   // no CTA exits while peers' multicasts may target its SMEM
#else
    // ==================== SIMT fp32 fallback ==================================
    __shared__ float As[BKF][128];
    __shared__ float Bs[BKF][128];

    const int tid = threadIdx.x;
    const int tx  = tid % 16;
    const int ty  = tid / 16;
    const int blockRow = blockIdx.x * BM;

    for (int half = 0; half < 2; half++) {
        const int blockCol = half * 128;
        const float* Ab = A + (size_t)blockRow * D;
        const float* Bb = W + (size_t)blockCol * D;

        float acc[8][8];
        #pragma unroll
        for (int i = 0; i < 8; i++)
            #pragma unroll
            for (int j = 0; j < 8; j++) acc[i][j] = 0.0f;

        const int lr = tid / 8;
        const int lc = tid % 8;

        for (int kt = 0; kt < D; kt += BKF) {
            __syncthreads();
            #pragma unroll
            for (int i = 0; i < 4; i++) {
                const int row = lr + i * 32;
                float4 va = *(const float4*)(Ab + (size_t)row * D + kt + lc * 4);
                As[lc * 4 + 0][row] = va.x;
                As[lc * 4 + 1][row] = va.y;
                As[lc * 4 + 2][row] = va.z;
                As[lc * 4 + 3][row] = va.w;
                float4 vb = *(const float4*)(Bb + (size_t)row * D + kt + lc * 4);
                Bs[lc * 4 + 0][row] = vb.x;
                Bs[lc * 4 + 1][row] = vb.y;
                Bs[lc * 4 + 2][row] = vb.z;
                Bs[lc * 4 + 3][row] = vb.w;
            }
            __syncthreads();

            #pragma unroll
            for (int k = 0; k < BKF; k++) {
                float a[8], b[8];
                *(float4*)&a[0] = *(const float4*)&As[k][ty * 8];
                *(float4*)&a[4] = *(const float4*)&As[k][ty * 8 + 4];
                *(float4*)&b[0] = *(const float4*)&Bs[k][tx * 8];
                *(float4*)&b[4] = *(const float4*)&Bs[k][tx * 8 + 4];
                #pragma unroll
                for (int i = 0; i < 8; i++)
                    #pragma unroll
                    for (int j = 0; j < 8; j++)
                        acc[i][j] = fmaf(a[i], b[j], acc[i][j]);
            }
        }

        #pragma unroll
        for (int i = 0; i < 8; i++) {
            const int row = blockRow + ty * 8 + i;
            float* Cr = C + (size_t)row * E + blockCol + tx * 8;
            *(float4*)(Cr + 0) = make_float4(acc[i][0], acc[i][1], acc[i][2], acc[i][3]);
            *(float4*)(Cr + 4) = make_float4(acc[i][4], acc[i][5], acc[i][6], acc[i][7]);
        }
    }
#endif
}

// ---------------------------------------------------------------------------
// Router: warp per token; lane owns 8 experts (unchanged from R4).
// ---------------------------------------------------------------------------
__global__ __launch_bounds__(256)
void router_topk_kernel(const float* __restrict__ C,
                        const float* __restrict__ bias,
                        float* __restrict__ wout,
                        float* __restrict__ iout) {
    const int t    = blockIdx.x * 8 + (threadIdx.x >> 5);
    const int lane = threadIdx.x & 31;

    const float4* row = (const float4*)(C + (size_t)t * 256) + lane * 2;
    float4 v0 = row[0], v1 = row[1];
    const float4* bp = (const float4*)bias + lane * 2;
    float4 b0 = __ldg(bp), b1 = __ldg(bp + 1);

    float sc[8] = {v0.x, v0.y, v0.z, v0.w, v1.x, v1.y, v1.z, v1.w};
    float bl[8] = {b0.x, b0.y, b0.z, b0.w, b1.x, b1.y, b1.z, b1.w};

    float m = sc[0];
    #pragma unroll
    for (int j = 1; j < 8; j++) m = fmaxf(m, sc[j]);
    #pragma unroll
    for (int off = 16; off > 0; off >>= 1)
        m = fmaxf(m, __shfl_xor_sync(0xffffffffu, m, off));

    float ex[8];
    float su = 0.0f;
    #pragma unroll
    for (int j = 0; j < 8; j++) { ex[j] = __expf(sc[j] - m); su += ex[j]; }
    #pragma unroll
    for (int off = 16; off > 0; off >>= 1)
        su += __shfl_xor_sync(0xffffffffu, su, off);
    const float inv = 1.0f / su;

    float prob[8], choice[8];
    #pragma unroll
    for (int j = 0; j < 8; j++) {
        prob[j]   = ex[j] * inv;
        choice[j] = prob[j] + bl[j];
    }

    float v = choice[0];
    int   li = 0;
    #pragma unroll
    for (int j = 1; j < 8; j++)
        if (choice[j] > v) { v = choice[j]; li = j; }

    #pragma unroll
    for (int k = 0; k < TOP_K; k++) {
        float g = v;
        #pragma unroll
        for (int off = 16; off > 0; off >>= 1)
            g = fmaxf(g, __shfl_xor_sync(0xffffffffu, g, off));
        unsigned mask = __ballot_sync(0xffffffffu, v == g);
        int src = __ffs(mask) - 1;
        if (lane == src) {
            float pw = 0.0f;
            #pragma unroll
            for (int j = 0; j < 8; j++)
                if (j == li) { pw = prob[j]; choice[j] = -INFINITY; }
            wout[(size_t)t * TOP_K + k] = pw * ROUTED_SCALE;
            iout[(size_t)t * TOP_K + k] = (float)(lane * 8 + li);
            v = choice[0]; li = 0;
            #pragma unroll
            for (int j = 1; j < 8; j++)
                if (choice[j] > v) { v = choice[j]; li = j; }
        }
    }
}

// ----------------------------- launch ---------------------------------------
typedef CUresult (*PFN_encodeTiled)(
    CUtensorMap*, CUtensorMapDataType, cuuint32_t, void*,
    const cuuint64_t*, const cuuint64_t*, const cuuint32_t*, const cuuint32_t*,
    CUtensorMapInterleave, CUtensorMapSwizzle, CUtensorMapL2promotion,
    CUtensorMapFloatOOBfill);

extern "C" void kernel_launch(void* const* d_in, const int* in_sizes, int n_in,
                              void* d_out, int out_size) {
    const float* H    = (const float*)d_in[0];  // [T, D]
    const float* W    = (const float*)d_in[1];  // [E, D]
    const float* bias = (const float*)d_in[2];  // [E]

    const int E = in_sizes[2];                  // 256
    const int D = in_sizes[1] / E;              // 4096
    const int T = in_sizes[0] / D;              // 16384

    float* out  = (float*)d_out;
    float* C    = out;
    float* wout = out + (size_t)T * E;
    float* iout = wout + (size_t)T * TOP_K;

    static bool s_ready = false;
    static CUtensorMap s_hi, s_lo;
    if (!s_ready) {
        cudaFuncSetAttribute(gemm_kernel,
                             cudaFuncAttributeMaxDynamicSharedMemorySize, DYN_SMEM);

        void* fn = nullptr;
        cudaDriverEntryPointQueryResult qr;
        cudaGetDriverEntryPoint("cuTensorMapEncodeTiled", &fn, cudaEnableDefault, &qr);
        PFN_encodeTiled encode = (PFN_encodeTiled)fn;

        void *dhi = nullptr, *dlo = nullptr;
        cudaGetSymbolAddress(&dhi, g_w_hi);
        cudaGetSymbolAddress(&dlo, g_w_lo);

        cuuint64_t dims[2]    = {(cuuint64_t)D, (cuuint64_t)E};
        cuuint64_t strides[1] = {(cuuint64_t)D * 2};
        cuuint32_t box[2]     = {32, 64};
        cuuint32_t es[2]      = {1, 1};
        if (encode) {
            encode(&s_hi, CU_TENSOR_MAP_DATA_TYPE_BFLOAT16, 2, dhi, dims, strides, box, es,
                   CU_TENSOR_MAP_INTERLEAVE_NONE, CU_TENSOR_MAP_SWIZZLE_64B,
                   CU_TENSOR_MAP_L2_PROMOTION_L2_128B, CU_TENSOR_MAP_FLOAT_OOB_FILL_NONE);
            encode(&s_lo, CU_TENSOR_MAP_DATA_TYPE_BFLOAT16, 2, dlo, dims, strides, box, es,
                   CU_TENSOR_MAP_INTERLEAVE_NONE, CU_TENSOR_MAP_SWIZZLE_64B,
                   CU_TENSOR_MAP_L2_PROMOTION_L2_128B, CU_TENSOR_MAP_FLOAT_OOB_FILL_NONE);
        }
        s_ready = true;
    }

    const int n4 = (E * D) / 4;
    split_w_kernel<<<(n4 + 255) / 256, 256>>>((const float4*)W, n4);
    gemm_kernel<<<T / BM, 256, DYN_SMEM>>>(H, C, D, E, W, s_hi, s_lo);
    router_topk_kernel<<<T / 8, 256>>>(C, bias, wout, iout);
}

// round 6
// speedup vs baseline: 1.0175x; 1.0175x over previous
#include <cuda_runtime.h>
#include <cuda.h>
#include <cuda_bf16.h>
#include <math.h>
#include <stdint.h>

// LongcatFlashTopkRouter: T=16384, D=4096, E=256
#define TOP_K 8
#define ROUTED_SCALE 1.5f

#if defined(__CUDA_ARCH__) && \
    (defined(__CUDA_ARCH_FEAT_SM103_ALL) || defined(__CUDA_ARCH_FEAT_SM100_ALL) || \
     defined(__CUDA_ARCH_FEAT_SM101_ALL))
#define HAS_TC 1
#else
#define HAS_TC 0
#endif

#define BM 128
#define BKF 32
#define NSTAGE 4
#define STAGE_BYTES 32768          // B_hi 16KB + B_lo 16KB (bf16, 256 x 32)
#define B_LO_OFF 16384
#define DYN_SMEM (NSTAGE * STAGE_BYTES + 1024)
#define CLUSTER_N 4
#define NTHREADS 288               // warps 0-7 producers, warp 8 MMA issuer

// idesc kind::f16 bf16: F32(1)<<4 | BF16(1)<<7 | BF16(1)<<10 | (N=128/8)<<17 | (M=128/16)<<24
#define IDESC 0x8200490u
#define TMEM_NCOLS 512
#define TMEM_A_BASE 256            // A stages: cols 256 + s*32 (hi 16, lo 16)

// W split into bf16 hi/lo once per launch (2MB each).
__device__ __align__(1024) static uint32_t g_w_hi[524288];
__device__ __align__(1024) static uint32_t g_w_lo[524288];

__device__ __forceinline__ uint32_t pack_bf16x2(float a, float b) {
    uint32_t d;
    asm("cvt.rn.bf16x2.f32 %0, %1, %2;" : "=r"(d) : "f"(a), "f"(b));
    return d;
}

__device__ __forceinline__ uint32_t smem_u32(const void* p) {
    uint32_t a;
    asm("{ .reg .u64 t; cvta.to.shared.u64 t, %1; cvt.u32.u64 %0, t; }" : "=r"(a) : "l"(p));
    return a;
}

// ------------------------- prep: split W fp32 -> bf16 hi/lo ------------------
__global__ __launch_bounds__(512)
void split_w_kernel(const float4* __restrict__ W4, int n4) {
    int i = blockIdx.x * 512 + threadIdx.x;
    if (i >= n4) return;
    float4 f = W4[i];
    uint32_t h0 = pack_bf16x2(f.y, f.x);
    uint32_t h1 = pack_bf16x2(f.w, f.z);
    float a0 = __uint_as_float(h0 << 16);
    float a1 = __uint_as_float(h0 & 0xFFFF0000u);
    float a2 = __uint_as_float(h1 << 16);
    float a3 = __uint_as_float(h1 & 0xFFFF0000u);
    uint32_t l0 = pack_bf16x2(f.y - a1, f.x - a0);
    uint32_t l1 = pack_bf16x2(f.w - a3, f.z - a2);
    g_w_hi[i * 2]     = h0;
    g_w_hi[i * 2 + 1] = h1;
    g_w_lo[i * 2]     = l0;
    g_w_lo[i * 2 + 1] = l1;
}

#if HAS_TC
// SW64 K-major descriptor: layout=4, version=1, SBO=32, LBO=1
__device__ __forceinline__ uint64_t mk_desc64(uint32_t addr) {
    const uint64_t base =
        (uint64_t(4) << 61) | (uint64_t(1) << 46) | (uint64_t(32) << 32) | (uint64_t(1) << 16);
    return base | ((uint64_t)(addr >> 4) & 0x3FFF);
}

// TS-form bf16 MMA: A in TMEM, B in SMEM
__device__ __forceinline__ void mma_ts(uint32_t d_tmem, uint32_t a_tmem, uint64_t b_desc,
                                       uint32_t en) {
    uint32_t z = 0;
    asm volatile(
        "{\n\t.reg .pred p;\n\t"
        "setp.ne.u32 p, %5, 0;\n\t"
        "tcgen05.mma.cta_group::1.kind::f16 [%0], [%1], %2, %3, {%4, %4, %4, %4}, p;\n\t}"
        :: "r"(d_tmem), "r"(a_tmem), "l"(b_desc), "r"(IDESC), "r"(z), "r"(en)
        : "memory");
}

__device__ __forceinline__ void mbar_init(uint32_t mbar, uint32_t cnt) {
    asm volatile("mbarrier.init.shared.b64 [%0], %1;" :: "r"(mbar), "r"(cnt) : "memory");
}

__device__ __forceinline__ void mbar_wait(uint32_t mbar, uint32_t parity) {
    asm volatile(
        "{\n\t.reg .pred P;\n\t"
        "WL_%=:\n\t"
        "mbarrier.try_wait.parity.acquire.cta.shared::cta.b64 P, [%0], %1, 0x989680;\n\t"
        "@P bra.uni WD_%=;\n\t"
        "bra.uni WL_%=;\n\t"
        "WD_%=:\n\t}"
        :: "r"(mbar), "r"(parity) : "memory");
}

__device__ __forceinline__ void mbar_arrive(uint32_t mbar) {
    asm volatile("mbarrier.arrive.release.cta.shared::cta.b64 _, [%0];"
                 :: "r"(mbar) : "memory");
}

__device__ __forceinline__ void mbar_expect_tx(uint32_t mbar, uint32_t bytes) {
    asm volatile("mbarrier.arrive.expect_tx.shared.b64 _, [%0], %1;"
                 :: "r"(mbar), "r"(bytes) : "memory");
}

__device__ __forceinline__ void tma_2d_mc(uint32_t dst, const void* map,
                                          int x, int y, uint32_t mbar, uint16_t mask) {
    asm volatile(
        "cp.async.bulk.tensor.2d.shared::cluster.global.tile.mbarrier::complete_tx::bytes"
        ".multicast::cluster [%0], [%1, {%2, %3}], [%4], %5;"
        :: "r"(dst), "l"(map), "r"(x), "r"(y), "r"(mbar), "h"(mask) : "memory");
}

__device__ __forceinline__ uint32_t cta_rank() {
    uint32_t r;
    asm("mov.u32 %0, %%cluster_ctarank;" : "=r"(r));
    return r;
}

#define TC_ALLOC(dst_smem, n) \
    asm volatile("tcgen05.alloc.cta_group::1.sync.aligned.shared::cta.b32 [%0], %1;" \
                 :: "r"(dst_smem), "r"((uint32_t)(n)) : "memory")
#define TC_RELINQ() \
    asm volatile("tcgen05.relinquish_alloc_permit.cta_group::1.sync.aligned;")
#define TC_DEALLOC(tm, n) \
    asm volatile("tcgen05.dealloc.cta_group::1.sync.aligned.b32 %0, %1;" :: "r"(tm), "r"((uint32_t)(n)))
#define TC_COMMIT_MC(mbar, mask) \
    asm volatile("tcgen05.commit.cta_group::1.mbarrier::arrive::one.shared::cluster" \
                 ".multicast::cluster.b64 [%0], %1;" \
                 :: "r"(mbar), "h"((uint16_t)(mask)) : "memory")
#define TC_FENCE_AFTER()  asm volatile("tcgen05.fence::after_thread_sync;" ::: "memory")
#define TC_FENCE_BEFORE() asm volatile("tcgen05.fence::before_thread_sync;" ::: "memory")
#define TC_WAIT_ST()  asm volatile("tcgen05.wait::st.sync.aligned;" ::: "memory")
#define TC_WAIT_LD()  asm volatile("tcgen05.wait::ld.sync.aligned;" ::: "memory")
#define CLUSTER_SYNC() do { \
    asm volatile("barrier.cluster.arrive.aligned;" ::: "memory"); \
    asm volatile("barrier.cluster.wait.aligned;" ::: "memory"); } while (0)

#define TC_ST_X8(addr, r) \
    asm volatile("tcgen05.st.sync.aligned.32x32b.x8.b32 [%0], {%1,%2,%3,%4,%5,%6,%7,%8};" \
        :: "r"(addr), "r"((r)[0]), "r"((r)[1]), "r"((r)[2]), "r"((r)[3]), \
           "r"((r)[4]), "r"((r)[5]), "r"((r)[6]), "r"((r)[7]) : "memory")

#define TC_LD_X32(r, addr) \
    asm volatile( \
        "tcgen05.ld.sync.aligned.32x32b.x32.b32 " \
        "{%0, %1, %2, %3, %4, %5, %6, %7, " \
        " %8, %9, %10, %11, %12, %13, %14, %15, " \
        " %16, %17, %18, %19, %20, %21, %22, %23, " \
        " %24, %25, %26, %27, %28, %29, %30, %31}, [%32];" \
        : "=r"((r)[0]),  "=r"((r)[1]),  "=r"((r)[2]),  "=r"((r)[3]), \
          "=r"((r)[4]),  "=r"((r)[5]),  "=r"((r)[6]),  "=r"((r)[7]), \
          "=r"((r)[8]),  "=r"((r)[9]),  "=r"((r)[10]), "=r"((r)[11]), \
          "=r"((r)[12]), "=r"((r)[13]), "=r"((r)[14]), "=r"((r)[15]), \
          "=r"((r)[16]), "=r"((r)[17]), "=r"((r)[18]), "=r"((r)[19]), \
          "=r"((r)[20]), "=r"((r)[21]), "=r"((r)[22]), "=r"((r)[23]), \
          "=r"((r)[24]), "=r"((r)[25]), "=r"((r)[26]), "=r"((r)[27]), \
          "=r"((r)[28]), "=r"((r)[29]), "=r"((r)[30]), "=r"((r)[31]) \
        : "r"(addr))
#endif  // HAS_TC

extern __shared__ char g_dyn_smem[];

__global__ __launch_bounds__(NTHREADS, 1) __cluster_dims__(CLUSTER_N, 1, 1)
void gemm_kernel(const float* __restrict__ A,   // [T, D]
                 float* __restrict__ C,         // [T, E]
                 int D, int E,
                 const float* __restrict__ W,   // fp32 W (fallback only)
                 const __grid_constant__ CUtensorMap tm_hi,
                 const __grid_constant__ CUtensorMap tm_lo) {
#if HAS_TC
    // ====== warp-specialized: warps 0-7 produce A (+warp0: B TMA); warp 8 MMA =====
    __shared__ uint32_t s_tmem;
    // [full_b x4][empt x4][full_a x4]
    __shared__ __align__(16) unsigned long long s_mbar[3 * NSTAGE];

    const int tid  = threadIdx.x;
    const int wid  = tid >> 5;
    const int lane = tid & 31;
    const uint32_t rank = cta_rank();

    uint32_t raw_u32   = smem_u32(g_dyn_smem);
    uint32_t btile_u32 = (raw_u32 + 1023u) & ~1023u;

    const uint32_t mb     = smem_u32(&s_mbar[0]);
    const uint32_t FULL_B = mb;
    const uint32_t EMPT   = mb + 32;
    const uint32_t FULL_A = mb + 64;

    if (wid == 0) TC_ALLOC(smem_u32(&s_tmem), TMEM_NCOLS);
    if (tid == 0) {
        #pragma unroll
        for (int s = 0; s < NSTAGE; s++) {
            mbar_init(FULL_B + s * 8, 1);          // expect_tx arrive
            mbar_init(EMPT   + s * 8, CLUSTER_N);  // 4 cluster commits
            mbar_init(FULL_A + s * 8, 8);          // 8 producer warps
        }
    }
    __syncthreads();
    CLUSTER_SYNC();   // mbars visible cluster-wide before any multicast TMA
    const uint32_t tmem = s_tmem;

    const int blockRow = blockIdx.x * BM;
    const int niter = D / BKF;            // 128

    if (wid < 8) {
        // ------------------------- A producers (+ TMA) -----------------------
        const int subp = wid & 3;
        const int kh   = wid >> 2;
        const float* aBase = A + (size_t)(blockRow + subp * 32 + lane) * D + kh * 16;

        float4 buf[4];
        #pragma unroll
        for (int q = 0; q < 4; q++) buf[q] = *(const float4*)(aBase + q * 4);

        for (int i = 0; i < niter; i++) {
            const int s = i & 3;
            const int r = i >> 2;

            if (r > 0) mbar_wait(EMPT + s * 8, (r - 1) & 1);

            // B TMA for this stage (warp 0 lane 0); runs ~NSTAGE ahead of MMA
            if (wid == 0 && lane == 0) {
                const uint32_t sb = btile_u32 + (uint32_t)s * STAGE_BYTES;
                mbar_expect_tx(FULL_B + s * 8, STAGE_BYTES);
                tma_2d_mc(sb + rank * 4096,            &tm_hi, i * 32, (int)rank * 64,
                          FULL_B + s * 8, (uint16_t)0xF);
                tma_2d_mc(sb + B_LO_OFF + rank * 4096, &tm_lo, i * 32, (int)rank * 64,
                          FULL_B + s * 8, (uint16_t)0xF);
            }

            // convert fp32 -> hi/lo bf16x2, store to TMEM stage s
            uint32_t hi[8], lo[8];
            #pragma unroll
            for (int q = 0; q < 4; q++) {
                float4 f = buf[q];
                uint32_t h0 = pack_bf16x2(f.y, f.x);
                uint32_t h1 = pack_bf16x2(f.w, f.z);
                float a0 = __uint_as_float(h0 << 16);
                float a1 = __uint_as_float(h0 & 0xFFFF0000u);
                float a2 = __uint_as_float(h1 << 16);
                float a3 = __uint_as_float(h1 & 0xFFFF0000u);
                hi[q * 2]     = h0;
                hi[q * 2 + 1] = h1;
                lo[q * 2]     = pack_bf16x2(f.y - a1, f.x - a0);
                lo[q * 2 + 1] = pack_bf16x2(f.w - a3, f.z - a2);
            }
            const uint32_t ac = tmem + ((uint32_t)subp << 21) +
                                TMEM_A_BASE + (uint32_t)s * 32 + (uint32_t)kh * 8;
            TC_ST_X8(ac, hi);
            TC_ST_X8(ac + 16, lo);
            TC_WAIT_ST();
            TC_FENCE_BEFORE();
            if (lane == 0) mbar_arrive(FULL_A + s * 8);

            // prefetch next A chunk
            if (i + 1 < niter) {
                const float* ap = aBase + (i + 1) * BKF;
                #pragma unroll
                for (int q = 0; q < 4; q++) buf[q] = *(const float4*)(ap + q * 4);
            }
        }
    } else if (lane == 0) {
        // ------------------------------ MMA issuer ---------------------------
        uint32_t en = 0;
        for (int i = 0; i < niter; i++) {
            const int s = i & 3;
            const int r = i >> 2;

            mbar_wait(FULL_A + s * 8, r & 1);
            mbar_wait(FULL_B + s * 8, r & 1);
            TC_FENCE_AFTER();

            const uint32_t sb = btile_u32 + (uint32_t)s * STAGE_BYTES;
            const uint64_t dBh = mk_desc64(sb);
            const uint64_t dBl = mk_desc64(sb + B_LO_OFF);
            const uint32_t ab = tmem + TMEM_A_BASE + (uint32_t)s * 32;
            #pragma unroll
            for (int ks = 0; ks < 2; ks++) {
                const uint64_t o = 2 * ks;          // K-step: 16 bf16 = 32B = 2 units
                const uint32_t aH = ab + ks * 8;
                const uint32_t aL = ab + 16 + ks * 8;
                mma_ts(tmem,       aH, dBh + o,       en);
                mma_ts(tmem + 128, aH, dBh + 512 + o, en);   // experts 128-255: +8KB
                en = 1;
                mma_ts(tmem,       aH, dBl + o,       1);
                mma_ts(tmem + 128, aH, dBl + 512 + o, 1);
                mma_ts(tmem,       aL, dBh + o,       1);
                mma_ts(tmem + 128, aL, dBh + 512 + o, 1);
            }
            TC_COMMIT_MC(EMPT + s * 8, 0xF);
        }
    }

    // drain: all stages' final (round-31) commits
    #pragma unroll
    for (int s = 0; s < NSTAGE; s++) mbar_wait(EMPT + s * 8, 1);
    TC_FENCE_AFTER();

    // epilogue: 8 warps; warps 0-3 cols 0-127, warps 4-7 cols 128-255
    if (wid < 8) {
        const int m  = blockRow + (wid & 3) * 32 + lane;
        const int c0 = (wid >> 2) * 128;
        #pragma unroll
        for (int cb = 0; cb < 128; cb += 32) {
            uint32_t rg[32];
            TC_LD_X32(rg, tmem + c0 + cb);
            TC_WAIT_LD();
            float* cr = C + (size_t)m * E + c0 + cb;
            #pragma unroll
            for (int q = 0; q < 8; q++) {
                *(float4*)(cr + q * 4) = make_float4(__uint_as_float(rg[q * 4 + 0]),
                                                     __uint_as_float(rg[q * 4 + 1]),
                                                     __uint_as_float(rg[q * 4 + 2]),
                                                     __uint_as_float(rg[q * 4 + 3]));
            }
        }
        TC_FENCE_BEFORE();
    }
    __syncthreads();
    if (wid == 0) {
        TC_RELINQ();
        TC_DEALLOC(tmem, TMEM_NCOLS);
    }
    CLUSTER_SYNC();
#else
    // ==================== SIMT fp32 fallback (288 threads) ===================
    __shared__ float As[BKF][128];
    __shared__ float Bs[BKF][128];

    const int tid = threadIdx.x;
    const int tx  = tid % 16;
    const int ty  = tid / 16;
    const int blockRow = blockIdx.x * BM;

    for (int half = 0; half < 2; half++) {
        const int blockCol = half * 128;
        const float* Ab = A + (size_t)blockRow * D;
        const float* Bb = W + (size_t)blockCol * D;

        float acc[8][8];
        #pragma unroll
        for (int i = 0; i < 8; i++)
            #pragma unroll
            for (int j = 0; j < 8; j++) acc[i][j] = 0.0f;

        for (int kt = 0; kt < D; kt += BKF) {
            __syncthreads();
            for (int idx = tid; idx < 128 * 8; idx += NTHREADS) {
                const int row = idx / 8;
                const int lc  = idx % 8;
                float4 va = *(const float4*)(Ab + (size_t)row * D + kt + lc * 4);
                As[lc * 4 + 0][row] = va.x;
                As[lc * 4 + 1][row] = va.y;
                As[lc * 4 + 2][row] = va.z;
                As[lc * 4 + 3][row] = va.w;
                float4 vb = *(const float4*)(Bb + (size_t)row * D + kt + lc * 4);
                Bs[lc * 4 + 0][row] = vb.x;
                Bs[lc * 4 + 1][row] = vb.y;
                Bs[lc * 4 + 2][row] = vb.z;
                Bs[lc * 4 + 3][row] = vb.w;
            }
            __syncthreads();

            if (tid < 256) {
                #pragma unroll
                for (int k = 0; k < BKF; k++) {
                    float a[8], b[8];
                    *(float4*)&a[0] = *(const float4*)&As[k][ty * 8];
                    *(float4*)&a[4] = *(const float4*)&As[k][ty * 8 + 4];
                    *(float4*)&b[0] = *(const float4*)&Bs[k][tx * 8];
                    *(float4*)&b[4] = *(const float4*)&Bs[k][tx * 8 + 4];
                    #pragma unroll
                    for (int i = 0; i < 8; i++)
                        #pragma unroll
                        for (int j = 0; j < 8; j++)
                            acc[i][j] = fmaf(a[i], b[j], acc[i][j]);
                }
            }
        }

        if (tid < 256) {
            #pragma unroll
            for (int i = 0; i < 8; i++) {
                const int row = blockRow + ty * 8 + i;
                float* Cr = C + (size_t)row * E + blockCol + tx * 8;
                *(float4*)(Cr + 0) = make_float4(acc[i][0], acc[i][1], acc[i][2], acc[i][3]);
                *(float4*)(Cr + 4) = make_float4(acc[i][4], acc[i][5], acc[i][6], acc[i][7]);
            }
        }
        __syncthreads();
    }
#endif
}

// ---------------------------------------------------------------------------
// Router: warp per token; lane owns 8 experts.
// ---------------------------------------------------------------------------
__global__ __launch_bounds__(256)
void router_topk_kernel(const float* __restrict__ C,
                        const float* __restrict__ bias,
                        float* __restrict__ wout,
                        float* __restrict__ iout) {
    const int t    = blockIdx.x * 8 + (threadIdx.x >> 5);
    const int lane = threadIdx.x & 31;

    const float4* row = (const float4*)(C + (size_t)t * 256) + lane * 2;
    float4 v0 = row[0], v1 = row[1];
    const float4* bp = (const float4*)bias + lane * 2;
    float4 b0 = __ldg(bp), b1 = __ldg(bp + 1);

    float sc[8] = {v0.x, v0.y, v0.z, v0.w, v1.x, v1.y, v1.z, v1.w};
    float bl[8] = {b0.x, b0.y, b0.z, b0.w, b1.x, b1.y, b1.z, b1.w};

    float m = sc[0];
    #pragma unroll
    for (int j = 1; j < 8; j++) m = fmaxf(m, sc[j]);
    #pragma unroll
    for (int off = 16; off > 0; off >>= 1)
        m = fmaxf(m, __shfl_xor_sync(0xffffffffu, m, off));

    float ex[8];
    float su = 0.0f;
    #pragma unroll
    for (int j = 0; j < 8; j++) { ex[j] = __expf(sc[j] - m); su += ex[j]; }
    #pragma unroll
    for (int off = 16; off > 0; off >>= 1)
        su += __shfl_xor_sync(0xffffffffu, su, off);
    const float inv = 1.0f / su;

    float prob[8], choice[8];
    #pragma unroll
    for (int j = 0; j < 8; j++) {
        prob[j]   = ex[j] * inv;
        choice[j] = prob[j] + bl[j];
    }

    float v = choice[0];
    int   li = 0;
    #pragma unroll
    for (int j = 1; j < 8; j++)
        if (choice[j] > v) { v = choice[j]; li = j; }

    #pragma unroll
    for (int k = 0; k < TOP_K; k++) {
        float g = v;
        #pragma unroll
        for (int off = 16; off > 0; off >>= 1)
            g = fmaxf(g, __shfl_xor_sync(0xffffffffu, g, off));
        unsigned mask = __ballot_sync(0xffffffffu, v == g);
        int src = __ffs(mask) - 1;
        if (lane == src) {
            float pw = 0.0f;
            #pragma unroll
            for (int j = 0; j < 8; j++)
                if (j == li) { pw = prob[j]; choice[j] = -INFINITY; }
            wout[(size_t)t * TOP_K + k] = pw * ROUTED_SCALE;
            iout[(size_t)t * TOP_K + k] = (float)(lane * 8 + li);
            v = choice[0]; li = 0;
            #pragma unroll
            for (int j = 1; j < 8; j++)
                if (choice[j] > v) { v = choice[j]; li = j; }
        }
    }
}

// ----------------------------- launch ---------------------------------------
typedef CUresult (*PFN_encodeTiled)(
    CUtensorMap*, CUtensorMapDataType, cuuint32_t, void*,
    const cuuint64_t*, const cuuint64_t*, const cuuint32_t*, const cuuint32_t*,
    CUtensorMapInterleave, CUtensorMapSwizzle, CUtensorMapL2promotion,
    CUtensorMapFloatOOBfill);

extern "C" void kernel_launch(void* const* d_in, const int* in_sizes, int n_in,
                              void* d_out, int out_size) {
    const float* H    = (const float*)d_in[0];  // [T, D]
    const float* W    = (const float*)d_in[1];  // [E, D]
    const float* bias = (const float*)d_in[2];  // [E]

    const int E = in_sizes[2];                  // 256
    const int D = in_sizes[1] / E;              // 4096
    const int T = in_sizes[0] / D;              // 16384

    float* out  = (float*)d_out;
    float* C    = out;
    float* wout = out + (size_t)T * E;
    float* iout = wout + (size_t)T * TOP_K;

    static bool s_ready = false;
    static CUtensorMap s_hi, s_lo;
    if (!s_ready) {
        cudaFuncSetAttribute(gemm_kernel,
                             cudaFuncAttributeMaxDynamicSharedMemorySize, DYN_SMEM);

        void* fn = nullptr;
        cudaDriverEntryPointQueryResult qr;
        cudaGetDriverEntryPoint("cuTensorMapEncodeTiled", &fn, cudaEnableDefault, &qr);
        PFN_encodeTiled encode = (PFN_encodeTiled)fn;

        void *dhi = nullptr, *dlo = nullptr;
        cudaGetSymbolAddress(&dhi, g_w_hi);
        cudaGetSymbolAddress(&dlo, g_w_lo);

        cuuint64_t dims[2]    = {(cuuint64_t)D, (cuuint64_t)E};
        cuuint64_t strides[1] = {(cuuint64_t)D * 2};
        cuuint32_t box[2]     = {32, 64};
        cuuint32_t es[2]      = {1, 1};
        if (encode) {
            encode(&s_hi, CU_TENSOR_MAP_DATA_TYPE_BFLOAT16, 2, dhi, dims, strides, box, es,
                   CU_TENSOR_MAP_INTERLEAVE_NONE, CU_TENSOR_MAP_SWIZZLE_64B,
                   CU_TENSOR_MAP_L2_PROMOTION_L2_128B, CU_TENSOR_MAP_FLOAT_OOB_FILL_NONE);
            encode(&s_lo, CU_TENSOR_MAP_DATA_TYPE_BFLOAT16, 2, dlo, dims, strides, box, es,
                   CU_TENSOR_MAP_INTERLEAVE_NONE, CU_TENSOR_MAP_SWIZZLE_64B,
                   CU_TENSOR_MAP_L2_PROMOTION_L2_128B, CU_TENSOR_MAP_FLOAT_OOB_FILL_NONE);
        }
        s_ready = true;
    }

    const int n4 = (E * D) / 4;
    split_w_kernel<<<(n4 + 511) / 512, 512>>>((const float4*)W, n4);
    gemm_kernel<<<T / BM, NTHREADS, DYN_SMEM>>>(H, C, D, E, W, s_hi, s_lo);
    router_topk_kernel<<<T / 8, 256>>>(C, bias, wout, iout);
}